// round 3
// baseline (speedup 1.0000x reference)
#include <cuda_runtime.h>
#include <cuda_bf16.h>

#define B_   8
#define C_   64
#define O_   64
#define H_   128
#define W_   128
#define HW_  16384
#define PAD_ 3
#define R_   49
#define HSTR 48            // halo row stride: rows 16 banks apart -> conflict-free LDS.64

// Scratch (device globals)
__device__ float g_y[B_ * C_ * HW_];     // y = (W1^T W2) x
__device__ float g_v[B_ * C_ * HW_];     // v = W3 x
__device__ float g_wt[B_ * R_ * HW_];    // softmax weights [b][r][hw]
__device__ float g_M[64 * 64];           // M = W1^T W2

// -------------------- f32x2 helpers --------------------
__device__ __forceinline__ unsigned long long pk2(float lo, float hi) {
    unsigned long long r;
    asm("mov.b64 %0, {%1, %2};" : "=l"(r) : "f"(lo), "f"(hi));
    return r;
}
__device__ __forceinline__ void fma2(unsigned long long& d,
                                     unsigned long long a, unsigned long long b) {
    asm("fma.rn.f32x2 %0, %1, %2, %0;" : "+l"(d) : "l"(a), "l"(b));
}
__device__ __forceinline__ void upk2(unsigned long long v, float& lo, float& hi) {
    asm("mov.b64 {%0, %1}, %2;" : "=f"(lo), "=f"(hi) : "l"(v));
}

// ---------------------------------------------------------------------------
// Kernel 0: M = W1^T W2   (64x64x64)
// ---------------------------------------------------------------------------
__global__ __launch_bounds__(256) void mat_kernel(
    const float* __restrict__ W1, const float* __restrict__ W2)
{
    __shared__ float s1[4096], s2[4096];
    const int tx = threadIdx.x;
    for (int i = tx; i < 4096; i += 256) { s1[i] = W1[i]; s2[i] = W2[i]; }
    __syncthreads();

    const int c   = tx >> 2;
    const int cp0 = (tx & 3) * 16;
    float acc[16];
#pragma unroll
    for (int j = 0; j < 16; j++) acc[j] = 0.0f;

    for (int o = 0; o < 64; o++) {
        const float a = s1[o * 64 + c];
#pragma unroll
        for (int j = 0; j < 16; j++)
            acc[j] = fmaf(a, s2[o * 64 + cp0 + j], acc[j]);
    }
#pragma unroll
    for (int j = 0; j < 16; j++) g_M[c * 64 + cp0 + j] = acc[j];
}

// ---------------------------------------------------------------------------
// Kernel 1: y = M x  (z=0)  and  v = W3 x  (z=1), f32x2 packed over out-pairs.
// ---------------------------------------------------------------------------
__device__ __forceinline__ int wswz(int c, int o) {
    return c * 64 + (o ^ ((c << 1) & 63));
}

__global__ __launch_bounds__(256) void qkv_kernel(
    const float* __restrict__ x, const float* __restrict__ W3)
{
    __shared__ __align__(16) float sX[64 * 128];
    __shared__ __align__(16) float sWp[64 * 64];

    const int b = blockIdx.y, z = blockIdx.z;
    const float* Wm = (z == 0) ? g_M : W3;
    float* outp     = (z == 0) ? g_y : g_v;

    const int tx = threadIdx.x;
    const int n0 = blockIdx.x * 128;

    for (int i = tx; i < 4096; i += 256) {
        const int o = i >> 6, c = i & 63;
        sWp[wswz(c, o)] = Wm[i];
    }
    const float* xb = x + (size_t)b * C_ * HW_ + n0;
    for (int i = tx; i < 2048; i += 256) {
        const int c = i >> 5, j = i & 31;
        *(float4*)&sX[c * 128 + j * 4] = *(const float4*)(xb + (size_t)c * HW_ + j * 4);
    }
    __syncthreads();

    const int pp = tx & 31;
    const int oo = (tx >> 5) * 8;

    unsigned long long acc[4][4];
#pragma unroll
    for (int p = 0; p < 4; p++)
#pragma unroll
        for (int j = 0; j < 4; j++) acc[p][j] = 0ULL;

#pragma unroll 8
    for (int c = 0; c < 64; c++) {
        const float2 xa = *(const float2*)&sX[c * 128 + 2 * pp];
        const float2 xc = *(const float2*)&sX[c * 128 + 64 + 2 * pp];
        const unsigned long long d0 = pk2(xa.x, xa.x);
        const unsigned long long d1 = pk2(xa.y, xa.y);
        const unsigned long long d2 = pk2(xc.x, xc.x);
        const unsigned long long d3 = pk2(xc.y, xc.y);
#pragma unroll
        for (int j = 0; j < 4; j++) {
            const unsigned long long w2 =
                *(const unsigned long long*)&sWp[wswz(c, oo + 2 * j)];
            fma2(acc[0][j], w2, d0);
            fma2(acc[1][j], w2, d1);
            fma2(acc[2][j], w2, d2);
            fma2(acc[3][j], w2, d3);
        }
    }

    float* ob = outp + (size_t)b * O_ * HW_ + n0;
#pragma unroll
    for (int j = 0; j < 4; j++) {
        float a0, a1, b0, b1, c0, c1, d0, d1;
        upk2(acc[0][j], a0, a1);
        upk2(acc[1][j], b0, b1);
        upk2(acc[2][j], c0, c1);
        upk2(acc[3][j], d0, d1);
        const int o = oo + 2 * j;
        *(float2*)(ob + (size_t)o * HW_ + 2 * pp)            = make_float2(a0, b0);
        *(float2*)(ob + (size_t)o * HW_ + 64 + 2 * pp)       = make_float2(c0, d0);
        *(float2*)(ob + (size_t)(o + 1) * HW_ + 2 * pp)      = make_float2(a1, b1);
        *(float2*)(ob + (size_t)(o + 1) * HW_ + 64 + 2 * pp) = make_float2(c1, d1);
    }
}

// ---------------------------------------------------------------------------
// Halo fill: 8 channels of [22 x 22] zero-padded tile, row stride HSTR.
// 128 threads.
// ---------------------------------------------------------------------------
__device__ __forceinline__ void fill_halo(
    float* sH, const float* __restrict__ src, int ch0, int h0, int w0, int tx)
{
#pragma unroll
    for (int cc = 0; cc < 8; cc++) {
        const float* sc = src + (size_t)(ch0 + cc) * HW_;
        float* dc = sH + cc * (22 * HSTR);
        for (int j = tx; j < 484; j += 128) {
            const int r   = j / 22;
            const int col = j - r * 22;
            const int hh  = h0 + r - PAD_;
            const int ww  = w0 + col - PAD_;
            float v = 0.0f;
            if (hh >= 0 && hh < H_ && ww >= 0 && ww < W_)
                v = sc[hh * W_ + ww];
            dc[r * HSTR + col] = v;
        }
    }
}

// ---------------------------------------------------------------------------
// Kernel 2: scores + softmax -> g_wt.  16x16 tile, 128 threads, 2 px/thread.
// s2[r] packs (score_px0, score_px1).  8-float row window -> 4 aligned LDS.64.
// ---------------------------------------------------------------------------
__global__ __launch_bounds__(128) void score_kernel(const float* __restrict__ x)
{
    __shared__ __align__(16) float sH[8 * 22 * HSTR];   // 33 KB

    const int b  = blockIdx.z;
    const int h0 = blockIdx.y * 16;
    const int w0 = blockIdx.x * 16;
    const int tx = threadIdx.x;
    const int py = tx >> 3;          // 0..15
    const int i  = tx & 7;           // px pair: cols 2i, 2i+1
    const int h  = h0 + py;
    const int wp = w0 + 2 * i;

    const float* yb = g_y + (size_t)b * C_ * HW_;
    const float* xb = x + (size_t)b * C_ * HW_ + h * W_ + wp;

    unsigned long long s2[49];
#pragma unroll
    for (int r = 0; r < 49; r++) s2[r] = 0ULL;

    for (int ch0 = 0; ch0 < 64; ch0 += 8) {
        fill_halo(sH, yb, ch0, h0, w0, tx);
        __syncthreads();

#pragma unroll
        for (int cc = 0; cc < 8; cc++) {
            const float2 qv = *(const float2*)(xb + (size_t)(ch0 + cc) * HW_);
            const unsigned long long q2 = pk2(qv.x, qv.y);
            const float* rowb = sH + cc * (22 * HSTR) + py * HSTR + 2 * i;
#pragma unroll
            for (int dh = 0; dh < 7; dh++) {
                const float* rp = rowb + dh * HSTR;
                const float2 p0 = *(const float2*)(rp);
                const float2 p1 = *(const float2*)(rp + 2);
                const float2 p2 = *(const float2*)(rp + 4);
                const float2 p3 = *(const float2*)(rp + 6);
                fma2(s2[dh * 7 + 0], q2, pk2(p0.x, p0.y));
                fma2(s2[dh * 7 + 1], q2, pk2(p0.y, p1.x));
                fma2(s2[dh * 7 + 2], q2, pk2(p1.x, p1.y));
                fma2(s2[dh * 7 + 3], q2, pk2(p1.y, p2.x));
                fma2(s2[dh * 7 + 4], q2, pk2(p2.x, p2.y));
                fma2(s2[dh * 7 + 5], q2, pk2(p2.y, p3.x));
                fma2(s2[dh * 7 + 6], q2, pk2(p3.x, p3.y));
            }
        }
        __syncthreads();
    }

    // Dual softmax (lo = px0, hi = px1)
    float sl[49], sh[49];
#pragma unroll
    for (int r = 0; r < 49; r++) upk2(s2[r], sl[r], sh[r]);

    float m0 = sl[0], m1 = sh[0];
#pragma unroll
    for (int r = 1; r < 49; r++) { m0 = fmaxf(m0, sl[r]); m1 = fmaxf(m1, sh[r]); }
    float u0 = 0.f, u1 = 0.f;
#pragma unroll
    for (int r = 0; r < 49; r++) {
        sl[r] = __expf(sl[r] - m0); u0 += sl[r];
        sh[r] = __expf(sh[r] - m1); u1 += sh[r];
    }
    const float i0 = __frcp_rn(u0), i1 = __frcp_rn(u1);

    float* wb = g_wt + (size_t)b * R_ * HW_ + h * W_ + wp;
#pragma unroll
    for (int r = 0; r < 49; r++)
        *(float2*)(wb + (size_t)r * HW_) = make_float2(sl[r] * i0, sh[r] * i1);
}

// ---------------------------------------------------------------------------
// Kernel 3: out[o,p] = sum_r wt[r,p] * v[o,p+dr].  Same 2 px/thread scheme.
// wt2[49] packed in regs for the whole kernel; one u64 acc per output channel.
// ---------------------------------------------------------------------------
__global__ __launch_bounds__(128) void weight_kernel(float* __restrict__ out)
{
    __shared__ __align__(16) float sH[8 * 22 * HSTR];

    const int b  = blockIdx.z;
    const int h0 = blockIdx.y * 16;
    const int w0 = blockIdx.x * 16;
    const int tx = threadIdx.x;
    const int py = tx >> 3;
    const int i  = tx & 7;
    const int h  = h0 + py;
    const int wp = w0 + 2 * i;

    const float* vb  = g_v + (size_t)b * C_ * HW_;
    const float* wtb = g_wt + (size_t)b * R_ * HW_ + h * W_ + wp;

    unsigned long long wt2[49];
#pragma unroll
    for (int r = 0; r < 49; r++) {
        const float2 t = *(const float2*)(wtb + (size_t)r * HW_);
        wt2[r] = pk2(t.x, t.y);
    }

    float* ob = out + (size_t)b * O_ * HW_ + h * W_ + wp;

    for (int ch0 = 0; ch0 < 64; ch0 += 8) {
        fill_halo(sH, vb, ch0, h0, w0, tx);
        __syncthreads();

#pragma unroll
        for (int o = 0; o < 8; o++) {
            unsigned long long acc = 0ULL;
            const float* rowb = sH + o * (22 * HSTR) + py * HSTR + 2 * i;
#pragma unroll
            for (int dh = 0; dh < 7; dh++) {
                const float* rp = rowb + dh * HSTR;
                const float2 p0 = *(const float2*)(rp);
                const float2 p1 = *(const float2*)(rp + 2);
                const float2 p2 = *(const float2*)(rp + 4);
                const float2 p3 = *(const float2*)(rp + 6);
                fma2(acc, wt2[dh * 7 + 0], pk2(p0.x, p0.y));
                fma2(acc, wt2[dh * 7 + 1], pk2(p0.y, p1.x));
                fma2(acc, wt2[dh * 7 + 2], pk2(p1.x, p1.y));
                fma2(acc, wt2[dh * 7 + 3], pk2(p1.y, p2.x));
                fma2(acc, wt2[dh * 7 + 4], pk2(p2.x, p2.y));
                fma2(acc, wt2[dh * 7 + 5], pk2(p2.y, p3.x));
                fma2(acc, wt2[dh * 7 + 6], pk2(p3.x, p3.y));
            }
            float a0, a1;
            upk2(acc, a0, a1);
            *(float2*)(ob + (size_t)(ch0 + o) * HW_) = make_float2(a0, a1);
        }
        __syncthreads();
    }
}

// ---------------------------------------------------------------------------
extern "C" void kernel_launch(void* const* d_in, const int* in_sizes, int n_in,
                              void* d_out, int out_size)
{
    const float* x  = (const float*)d_in[0];
    const float* W1 = (const float*)d_in[1];
    const float* W2 = (const float*)d_in[2];
    const float* W3 = (const float*)d_in[3];
    float* out = (float*)d_out;
    (void)in_sizes; (void)n_in; (void)out_size;

    mat_kernel<<<1, 256>>>(W1, W2);
    qkv_kernel<<<dim3(HW_ / 128, B_, 2), 256>>>(x, W3);
    score_kernel<<<dim3(W_ / 16, H_ / 16, B_), 128>>>(x);
    weight_kernel<<<dim3(W_ / 16, H_ / 16, B_), 128>>>(out);
}

// round 4
// speedup vs baseline: 1.2034x; 1.2034x over previous
#include <cuda_runtime.h>
#include <cuda_bf16.h>

#define B_   8
#define C_   64
#define O_   64
#define H_   128
#define W_   128
#define HW_  16384
#define PAD_ 3
#define R_   49
#define HSTR 48   // halo row stride; 16-lane LDS.64 phases span 2 rows -> conflict-free

// Scratch (device globals)
__device__ float g_y[B_ * C_ * HW_];     // y = (W1^T W2) x
__device__ float g_v[B_ * C_ * HW_];     // v = W3 x
__device__ float g_wt[B_ * R_ * HW_];    // softmax weights [b][r][hw]
__device__ float g_M[64 * 64];           // M = W1^T W2

// -------------------- f32x2 helpers --------------------
__device__ __forceinline__ unsigned long long pk2(float lo, float hi) {
    unsigned long long r;
    asm("mov.b64 %0, {%1, %2};" : "=l"(r) : "f"(lo), "f"(hi));
    return r;
}
__device__ __forceinline__ void fma2(unsigned long long& d,
                                     unsigned long long a, unsigned long long b) {
    asm("fma.rn.f32x2 %0, %1, %2, %0;" : "+l"(d) : "l"(a), "l"(b));
}
__device__ __forceinline__ void upk2(unsigned long long v, float& lo, float& hi) {
    asm("mov.b64 {%0, %1}, %2;" : "=f"(lo), "=f"(hi) : "l"(v));
}

// ---------------------------------------------------------------------------
// Kernel 0: M = W1^T W2   (64x64x64)
// ---------------------------------------------------------------------------
__global__ __launch_bounds__(256) void mat_kernel(
    const float* __restrict__ W1, const float* __restrict__ W2)
{
    __shared__ float s1[4096], s2[4096];
    const int tx = threadIdx.x;
    for (int i = tx; i < 4096; i += 256) { s1[i] = W1[i]; s2[i] = W2[i]; }
    __syncthreads();

    const int c   = tx >> 2;
    const int cp0 = (tx & 3) * 16;
    float acc[16];
#pragma unroll
    for (int j = 0; j < 16; j++) acc[j] = 0.0f;

    for (int o = 0; o < 64; o++) {
        const float a = s1[o * 64 + c];
#pragma unroll
        for (int j = 0; j < 16; j++)
            acc[j] = fmaf(a, s2[o * 64 + cp0 + j], acc[j]);
    }
#pragma unroll
    for (int j = 0; j < 16; j++) g_M[c * 64 + cp0 + j] = acc[j];
}

// ---------------------------------------------------------------------------
// Kernel 1: y = M x  (z=0)  and  v = W3 x  (z=1), f32x2 packed over out-pairs.
// ---------------------------------------------------------------------------
__device__ __forceinline__ int wswz(int c, int o) {
    return c * 64 + (o ^ ((c << 1) & 63));
}

__global__ __launch_bounds__(256) void qkv_kernel(
    const float* __restrict__ x, const float* __restrict__ W3)
{
    __shared__ __align__(16) float sX[64 * 128];
    __shared__ __align__(16) float sWp[64 * 64];

    const int b = blockIdx.y, z = blockIdx.z;
    const float* Wm = (z == 0) ? g_M : W3;
    float* outp     = (z == 0) ? g_y : g_v;

    const int tx = threadIdx.x;
    const int n0 = blockIdx.x * 128;

    for (int i = tx; i < 4096; i += 256) {
        const int o = i >> 6, c = i & 63;
        sWp[wswz(c, o)] = Wm[i];
    }
    const float* xb = x + (size_t)b * C_ * HW_ + n0;
    for (int i = tx; i < 2048; i += 256) {
        const int c = i >> 5, j = i & 31;
        *(float4*)&sX[c * 128 + j * 4] = *(const float4*)(xb + (size_t)c * HW_ + j * 4);
    }
    __syncthreads();

    const int pp = tx & 31;
    const int oo = (tx >> 5) * 8;

    unsigned long long acc[4][4];
#pragma unroll
    for (int p = 0; p < 4; p++)
#pragma unroll
        for (int j = 0; j < 4; j++) acc[p][j] = 0ULL;

#pragma unroll 8
    for (int c = 0; c < 64; c++) {
        const float2 xa = *(const float2*)&sX[c * 128 + 2 * pp];
        const float2 xc = *(const float2*)&sX[c * 128 + 64 + 2 * pp];
        const unsigned long long d0 = pk2(xa.x, xa.x);
        const unsigned long long d1 = pk2(xa.y, xa.y);
        const unsigned long long d2 = pk2(xc.x, xc.x);
        const unsigned long long d3 = pk2(xc.y, xc.y);
#pragma unroll
        for (int j = 0; j < 4; j++) {
            const unsigned long long w2 =
                *(const unsigned long long*)&sWp[wswz(c, oo + 2 * j)];
            fma2(acc[0][j], w2, d0);
            fma2(acc[1][j], w2, d1);
            fma2(acc[2][j], w2, d2);
            fma2(acc[3][j], w2, d3);
        }
    }

    float* ob = outp + (size_t)b * O_ * HW_ + n0;
#pragma unroll
    for (int j = 0; j < 4; j++) {
        float a0, a1, b0, b1, c0, c1, d0, d1;
        upk2(acc[0][j], a0, a1);
        upk2(acc[1][j], b0, b1);
        upk2(acc[2][j], c0, c1);
        upk2(acc[3][j], d0, d1);
        const int o = oo + 2 * j;
        *(float2*)(ob + (size_t)o * HW_ + 2 * pp)            = make_float2(a0, b0);
        *(float2*)(ob + (size_t)o * HW_ + 64 + 2 * pp)       = make_float2(c0, d0);
        *(float2*)(ob + (size_t)(o + 1) * HW_ + 2 * pp)      = make_float2(a1, b1);
        *(float2*)(ob + (size_t)(o + 1) * HW_ + 64 + 2 * pp) = make_float2(c1, d1);
    }
}

// ---------------------------------------------------------------------------
// Halo fill: 8 channels of [22 x 22] zero-padded tile, row stride HSTR. 256 thr.
// ---------------------------------------------------------------------------
__device__ __forceinline__ void fill_halo(
    float* sH, const float* __restrict__ src, int ch0, int h0, int w0, int tx)
{
    for (int idx = tx; idx < 8 * 484; idx += 256) {
        const int cc  = idx / 484;
        const int rem = idx - cc * 484;
        const int r   = rem / 22;
        const int col = rem - r * 22;
        const int hh  = h0 + r - PAD_;
        const int ww  = w0 + col - PAD_;
        float v = 0.0f;
        if (hh >= 0 && hh < H_ && ww >= 0 && ww < W_)
            v = src[(size_t)(ch0 + cc) * HW_ + hh * W_ + ww];
        sH[cc * (22 * HSTR) + r * HSTR + col] = v;
    }
}

// Load an 8-float window (4 aligned LDS.64) and feed 7 packed taps.
#define WINDOW_FMA7(ACCBASE, MUL_OF_TAP, rp)                        \
    do {                                                            \
        const float2 p0 = *(const float2*)(rp);                     \
        const float2 p1 = *(const float2*)((rp) + 2);               \
        const float2 p2 = *(const float2*)((rp) + 4);               \
        const float2 p3 = *(const float2*)((rp) + 6);               \
        fma2(ACCBASE[0], MUL_OF_TAP[0], pk2(p0.x, p0.y));           \
        fma2(ACCBASE[1], MUL_OF_TAP[1], pk2(p0.y, p1.x));           \
        fma2(ACCBASE[2], MUL_OF_TAP[2], pk2(p1.x, p1.y));           \
        fma2(ACCBASE[3], MUL_OF_TAP[3], pk2(p1.y, p2.x));           \
        fma2(ACCBASE[4], MUL_OF_TAP[4], pk2(p2.x, p2.y));           \
        fma2(ACCBASE[5], MUL_OF_TAP[5], pk2(p2.y, p3.x));           \
        fma2(ACCBASE[6], MUL_OF_TAP[6], pk2(p3.x, p3.y));           \
    } while (0)

// ---------------------------------------------------------------------------
// Kernel 2: scores + softmax. 16x16 tile, 256 thr = 128 px-pairs x 2 tap-halves.
// half0: dh 0..3 (taps 0..27), half1: dh 4..6 (taps 28..48).
// ---------------------------------------------------------------------------
template<int NDH, int DH0>
__device__ __forceinline__ void score_accum(
    unsigned long long* s2, const float* sH,
    const float* __restrict__ xb, int ch0, int py, int i)
{
#pragma unroll
    for (int cc = 0; cc < 8; cc++) {
        const float2 qv = *(const float2*)(xb + (size_t)(ch0 + cc) * HW_);
        const unsigned long long q2 = pk2(qv.x, qv.y);
        unsigned long long qm[7];
#pragma unroll
        for (int j = 0; j < 7; j++) qm[j] = q2;
        const float* rowb = sH + cc * (22 * HSTR) + (py + DH0) * HSTR + 2 * i;
#pragma unroll
        for (int d = 0; d < NDH; d++) {
            const float* rp = rowb + d * HSTR;
            WINDOW_FMA7((&s2[d * 7]), qm, rp);
        }
    }
}

__global__ __launch_bounds__(256, 2) void score_kernel(const float* __restrict__ x)
{
    __shared__ __align__(16) float sH[8 * 22 * HSTR];   // 33 KB
    __shared__ float2 xch[256];

    const int tx   = threadIdx.x;
    const int pair = tx & 127;
    const int half = tx >> 7;
    const int py = pair >> 3, i = pair & 7;
    const int b  = blockIdx.z;
    const int h0 = blockIdx.y * 16, w0 = blockIdx.x * 16;
    const int h  = h0 + py, wp = w0 + 2 * i;

    const float* yb = g_y + (size_t)b * C_ * HW_;
    const float* xb = x + (size_t)b * C_ * HW_ + h * W_ + wp;

    unsigned long long s2[28];
#pragma unroll
    for (int r = 0; r < 28; r++) s2[r] = 0ULL;

    for (int ch0 = 0; ch0 < 64; ch0 += 8) {
        fill_halo(sH, yb, ch0, h0, w0, tx);
        __syncthreads();
        if (half == 0) score_accum<4, 0>(s2, sH, xb, ch0, py, i);
        else           score_accum<3, 4>(s2, sH, xb, ch0, py, i);
        __syncthreads();
    }

    // partial max over own taps
    float ml = -1e30f, mh = -1e30f;
    if (half == 0) {
#pragma unroll
        for (int r = 0; r < 28; r++) {
            float a, c; upk2(s2[r], a, c);
            ml = fmaxf(ml, a); mh = fmaxf(mh, c);
        }
    } else {
#pragma unroll
        for (int r = 0; r < 21; r++) {
            float a, c; upk2(s2[r], a, c);
            ml = fmaxf(ml, a); mh = fmaxf(mh, c);
        }
    }
    xch[tx] = make_float2(ml, mh);
    __syncthreads();
    {
        const float2 om = xch[tx ^ 128];
        ml = fmaxf(ml, om.x); mh = fmaxf(mh, om.y);
    }
    __syncthreads();

    // exp (in place, packed) + partial sums
    float sl = 0.f, shh = 0.f;
    if (half == 0) {
#pragma unroll
        for (int r = 0; r < 28; r++) {
            float a, c; upk2(s2[r], a, c);
            a = __expf(a - ml); c = __expf(c - mh);
            sl += a; shh += c;
            s2[r] = pk2(a, c);
        }
    } else {
#pragma unroll
        for (int r = 0; r < 21; r++) {
            float a, c; upk2(s2[r], a, c);
            a = __expf(a - ml); c = __expf(c - mh);
            sl += a; shh += c;
            s2[r] = pk2(a, c);
        }
    }
    xch[tx] = make_float2(sl, shh);
    __syncthreads();
    const float2 os = xch[tx ^ 128];
    const float il = __frcp_rn(sl + os.x);
    const float ih = __frcp_rn(shh + os.y);

    float* wb = g_wt + (size_t)b * R_ * HW_ + h * W_ + wp;
    if (half == 0) {
#pragma unroll
        for (int r = 0; r < 28; r++) {
            float a, c; upk2(s2[r], a, c);
            *(float2*)(wb + (size_t)r * HW_) = make_float2(a * il, c * ih);
        }
    } else {
#pragma unroll
        for (int r = 0; r < 21; r++) {
            float a, c; upk2(s2[r], a, c);
            *(float2*)(wb + (size_t)(r + 28) * HW_) = make_float2(a * il, c * ih);
        }
    }
}

// ---------------------------------------------------------------------------
// Kernel 3: weighting. Same decomposition; each half accumulates partial
// outputs over its taps; half1's partials combined via smem.
// ---------------------------------------------------------------------------
template<int NDH, int DH0>
__device__ __forceinline__ void weight_accum(
    unsigned long long* acc2, const unsigned long long* wt2,
    const float* sH, int py, int i)
{
#pragma unroll
    for (int o = 0; o < 8; o++) {
        const float* rowb = sH + o * (22 * HSTR) + (py + DH0) * HSTR + 2 * i;
#pragma unroll
        for (int d = 0; d < NDH; d++) {
            const float* rp = rowb + d * HSTR;
            unsigned long long* a1 = &acc2[o];
            const float2 p0 = *(const float2*)(rp);
            const float2 p1 = *(const float2*)(rp + 2);
            const float2 p2 = *(const float2*)(rp + 4);
            const float2 p3 = *(const float2*)(rp + 6);
            fma2(*a1, wt2[d * 7 + 0], pk2(p0.x, p0.y));
            fma2(*a1, wt2[d * 7 + 1], pk2(p0.y, p1.x));
            fma2(*a1, wt2[d * 7 + 2], pk2(p1.x, p1.y));
            fma2(*a1, wt2[d * 7 + 3], pk2(p1.y, p2.x));
            fma2(*a1, wt2[d * 7 + 4], pk2(p2.x, p2.y));
            fma2(*a1, wt2[d * 7 + 5], pk2(p2.y, p3.x));
            fma2(*a1, wt2[d * 7 + 6], pk2(p3.x, p3.y));
        }
    }
}

__global__ __launch_bounds__(256, 2) void weight_kernel(float* __restrict__ out)
{
    __shared__ __align__(16) float sH[8 * 22 * HSTR];   // 33 KB
    __shared__ float2 pbuf[8 * 128];                    // 8 KB

    const int tx   = threadIdx.x;
    const int pair = tx & 127;
    const int half = tx >> 7;
    const int py = pair >> 3, i = pair & 7;
    const int b  = blockIdx.z;
    const int h0 = blockIdx.y * 16, w0 = blockIdx.x * 16;
    const int h  = h0 + py, wp = w0 + 2 * i;

    const float* vb  = g_v + (size_t)b * C_ * HW_;
    const float* wtb = g_wt + (size_t)b * R_ * HW_ + h * W_ + wp;

    unsigned long long wt2[28];
    if (half == 0) {
#pragma unroll
        for (int r = 0; r < 28; r++) {
            const float2 t = *(const float2*)(wtb + (size_t)r * HW_);
            wt2[r] = pk2(t.x, t.y);
        }
    } else {
#pragma unroll
        for (int r = 0; r < 21; r++) {
            const float2 t = *(const float2*)(wtb + (size_t)(r + 28) * HW_);
            wt2[r] = pk2(t.x, t.y);
        }
    }

    float* ob = out + (size_t)b * O_ * HW_ + h * W_ + wp;

    for (int ch0 = 0; ch0 < 64; ch0 += 8) {
        fill_halo(sH, vb, ch0, h0, w0, tx);
        __syncthreads();

        unsigned long long acc2[8];
#pragma unroll
        for (int o = 0; o < 8; o++) acc2[o] = 0ULL;

        if (half == 0) weight_accum<4, 0>(acc2, wt2, sH, py, i);
        else           weight_accum<3, 4>(acc2, wt2, sH, py, i);

        if (half == 1) {
#pragma unroll
            for (int o = 0; o < 8; o++) {
                float a, c; upk2(acc2[o], a, c);
                pbuf[o * 128 + pair] = make_float2(a, c);
            }
        }
        __syncthreads();
        if (half == 0) {
#pragma unroll
            for (int o = 0; o < 8; o++) {
                const float2 t = pbuf[o * 128 + pair];
                float a, c; upk2(acc2[o], a, c);
                *(float2*)(ob + (size_t)(ch0 + o) * HW_) =
                    make_float2(a + t.x, c + t.y);
            }
        }
        __syncthreads();
    }
}

// ---------------------------------------------------------------------------
extern "C" void kernel_launch(void* const* d_in, const int* in_sizes, int n_in,
                              void* d_out, int out_size)
{
    const float* x  = (const float*)d_in[0];
    const float* W1 = (const float*)d_in[1];
    const float* W2 = (const float*)d_in[2];
    const float* W3 = (const float*)d_in[3];
    float* out = (float*)d_out;
    (void)in_sizes; (void)n_in; (void)out_size;

    mat_kernel<<<1, 256>>>(W1, W2);
    qkv_kernel<<<dim3(HW_ / 128, B_, 2), 256>>>(x, W3);
    score_kernel<<<dim3(W_ / 16, H_ / 16, B_), 256>>>(x);
    weight_kernel<<<dim3(W_ / 16, H_ / 16, B_), 256>>>(out);
}

// round 5
// speedup vs baseline: 1.5299x; 1.2713x over previous
#include <cuda_runtime.h>
#include <cuda_bf16.h>

#define B_   8
#define C_   64
#define O_   64
#define H_   128
#define W_   128
#define HW_  16384
#define PAD_ 3
#define R_   49
#define HSTR 48                 // halo row stride (floats): conflict-free LDS.128 phases
#define CH_STRIDE (22 * HSTR)   // 1056 floats per halo channel

// Scratch (device globals)
__device__ float g_y[B_ * C_ * HW_];     // y = (W1^T W2) x
__device__ float g_v[B_ * C_ * HW_];     // v = W3 x
__device__ float g_wt[B_ * R_ * HW_];    // softmax weights [b][r][hw]
__device__ float g_M[64 * 64];           // M = W1^T W2

// -------------------- f32x2 helpers (qkv only) --------------------
__device__ __forceinline__ unsigned long long pk2(float lo, float hi) {
    unsigned long long r;
    asm("mov.b64 %0, {%1, %2};" : "=l"(r) : "f"(lo), "f"(hi));
    return r;
}
__device__ __forceinline__ void fma2(unsigned long long& d,
                                     unsigned long long a, unsigned long long b) {
    asm("fma.rn.f32x2 %0, %1, %2, %0;" : "+l"(d) : "l"(a), "l"(b));
}
__device__ __forceinline__ void upk2(unsigned long long v, float& lo, float& hi) {
    asm("mov.b64 {%0, %1}, %2;" : "=f"(lo), "=f"(hi) : "l"(v));
}

// ---------------------------------------------------------------------------
// Kernel 0: M = W1^T W2   (64x64x64)
// ---------------------------------------------------------------------------
__global__ __launch_bounds__(256) void mat_kernel(
    const float* __restrict__ W1, const float* __restrict__ W2)
{
    __shared__ float s1[4096], s2[4096];
    const int tx = threadIdx.x;
    for (int i = tx; i < 4096; i += 256) { s1[i] = W1[i]; s2[i] = W2[i]; }
    __syncthreads();

    const int c   = tx >> 2;
    const int cp0 = (tx & 3) * 16;
    float acc[16];
#pragma unroll
    for (int j = 0; j < 16; j++) acc[j] = 0.0f;

    for (int o = 0; o < 64; o++) {
        const float a = s1[o * 64 + c];
#pragma unroll
        for (int j = 0; j < 16; j++)
            acc[j] = fmaf(a, s2[o * 64 + cp0 + j], acc[j]);
    }
#pragma unroll
    for (int j = 0; j < 16; j++) g_M[c * 64 + cp0 + j] = acc[j];
}

// ---------------------------------------------------------------------------
// Kernel 1 (fused): y = M x  AND  v = W3 x, f32x2 packed over out-pairs.
// grid (HW/128, B), 256 threads. x staged once; both weight mats in smem.
// ---------------------------------------------------------------------------
__device__ __forceinline__ int wswz(int c, int o) {
    return c * 64 + (o ^ ((c << 1) & 63));
}

__global__ __launch_bounds__(256) void qkv_kernel(
    const float* __restrict__ x, const float* __restrict__ W3)
{
    __shared__ __align__(16) float sX[64 * 128];   // 32 KB
    __shared__ __align__(16) float sWa[64 * 64];   // 16 KB (M)
    __shared__ __align__(16) float sWb[64 * 64];   // 16 KB (W3)

    const int b  = blockIdx.y;
    const int tx = threadIdx.x;
    const int n0 = blockIdx.x * 128;

    for (int i = tx; i < 4096; i += 256) {
        const int o = i >> 6, c = i & 63;
        sWa[wswz(c, o)] = g_M[i];
        sWb[wswz(c, o)] = W3[i];
    }
    const float* xb = x + (size_t)b * C_ * HW_ + n0;
    for (int i = tx; i < 2048; i += 256) {
        const int c = i >> 5, j = i & 31;
        *(float4*)&sX[c * 128 + j * 4] = *(const float4*)(xb + (size_t)c * HW_ + j * 4);
    }
    __syncthreads();

    const int pp = tx & 31;
    const int oo = (tx >> 5) * 8;

    unsigned long long accA[4][4], accB[4][4];
#pragma unroll
    for (int p = 0; p < 4; p++)
#pragma unroll
        for (int j = 0; j < 4; j++) { accA[p][j] = 0ULL; accB[p][j] = 0ULL; }

#pragma unroll 4
    for (int c = 0; c < 64; c++) {
        const float2 xa = *(const float2*)&sX[c * 128 + 2 * pp];
        const float2 xc = *(const float2*)&sX[c * 128 + 64 + 2 * pp];
        const unsigned long long d0 = pk2(xa.x, xa.x);
        const unsigned long long d1 = pk2(xa.y, xa.y);
        const unsigned long long d2 = pk2(xc.x, xc.x);
        const unsigned long long d3 = pk2(xc.y, xc.y);
#pragma unroll
        for (int j = 0; j < 4; j++) {
            const int sw = wswz(c, oo + 2 * j);
            const unsigned long long wa = *(const unsigned long long*)&sWa[sw];
            const unsigned long long wb = *(const unsigned long long*)&sWb[sw];
            fma2(accA[0][j], wa, d0); fma2(accA[1][j], wa, d1);
            fma2(accA[2][j], wa, d2); fma2(accA[3][j], wa, d3);
            fma2(accB[0][j], wb, d0); fma2(accB[1][j], wb, d1);
            fma2(accB[2][j], wb, d2); fma2(accB[3][j], wb, d3);
        }
    }

    float* oy = g_y + (size_t)b * O_ * HW_ + n0;
    float* ov = g_v + (size_t)b * O_ * HW_ + n0;
#pragma unroll
    for (int j = 0; j < 4; j++) {
        const int o = oo + 2 * j;
        float a0, a1, b0, b1, c0, c1, d0, d1;
        upk2(accA[0][j], a0, a1); upk2(accA[1][j], b0, b1);
        upk2(accA[2][j], c0, c1); upk2(accA[3][j], d0, d1);
        *(float2*)(oy + (size_t)o * HW_ + 2 * pp)            = make_float2(a0, b0);
        *(float2*)(oy + (size_t)o * HW_ + 64 + 2 * pp)       = make_float2(c0, d0);
        *(float2*)(oy + (size_t)(o + 1) * HW_ + 2 * pp)      = make_float2(a1, b1);
        *(float2*)(oy + (size_t)(o + 1) * HW_ + 64 + 2 * pp) = make_float2(c1, d1);
        upk2(accB[0][j], a0, a1); upk2(accB[1][j], b0, b1);
        upk2(accB[2][j], c0, c1); upk2(accB[3][j], d0, d1);
        *(float2*)(ov + (size_t)o * HW_ + 2 * pp)            = make_float2(a0, b0);
        *(float2*)(ov + (size_t)o * HW_ + 64 + 2 * pp)       = make_float2(c0, d0);
        *(float2*)(ov + (size_t)(o + 1) * HW_ + 2 * pp)      = make_float2(a1, b1);
        *(float2*)(ov + (size_t)(o + 1) * HW_ + 64 + 2 * pp) = make_float2(c1, d1);
    }
}

// ---------------------------------------------------------------------------
// Halo fill: 8 channels of [22 x 22] zero-padded tile, stride HSTR. 256 thr.
// ---------------------------------------------------------------------------
__device__ __forceinline__ void fill_halo(
    float* sH, const float* __restrict__ src, int ch0, int h0, int w0, int tx)
{
    for (int idx = tx; idx < 8 * 484; idx += 256) {
        const int cc  = idx / 484;
        const int rem = idx - cc * 484;
        const int r   = rem / 22;
        const int col = rem - r * 22;
        const int hh  = h0 + r - PAD_;
        const int ww  = w0 + col - PAD_;
        float v = 0.0f;
        if (hh >= 0 && hh < H_ && ww >= 0 && ww < W_)
            v = src[(size_t)(ch0 + cc) * HW_ + hh * W_ + ww];
        sH[cc * CH_STRIDE + r * HSTR + col] = v;
    }
}

// Load 12-float window as 3 aligned LDS.128 into a register array.
__device__ __forceinline__ void load_win(float* win, const float* rp) {
    const float4 A = *(const float4*)(rp);
    const float4 Bv = *(const float4*)(rp + 4);
    const float4 Cv = *(const float4*)(rp + 8);
    win[0] = A.x;  win[1] = A.y;  win[2] = A.z;  win[3] = A.w;
    win[4] = Bv.x; win[5] = Bv.y; win[6] = Bv.z; win[7] = Bv.w;
    win[8] = Cv.x; win[9] = Cv.y; win[10] = Cv.z; win[11] = Cv.w;
}

// ---------------------------------------------------------------------------
// Kernel 2: scores + softmax. 16x16 tile, 256 thr = 64 quads x 4 dh-groups.
// Group g<3 handles dh {2g,2g+1}; g=3 handles dh 6. Quad = 4 aligned pixels.
// ---------------------------------------------------------------------------
template<int NDH, int DH0>
__device__ __forceinline__ void score_accum(
    float s[][4], const float* sH, const float* sX, int quad, int py, int qx4)
{
#pragma unroll
    for (int cc = 0; cc < 8; cc++) {
        const float4 q4 = *(const float4*)&sX[cc * 256 + 4 * quad];
        const float* rowb = sH + cc * CH_STRIDE + (py + DH0) * HSTR + qx4;
#pragma unroll
        for (int d = 0; d < NDH; d++) {
            float win[12];
            load_win(win, rowb + d * HSTR);
#pragma unroll
            for (int dw = 0; dw < 7; dw++) {
                s[d * 7 + dw][0] = fmaf(q4.x, win[dw + 0], s[d * 7 + dw][0]);
                s[d * 7 + dw][1] = fmaf(q4.y, win[dw + 1], s[d * 7 + dw][1]);
                s[d * 7 + dw][2] = fmaf(q4.z, win[dw + 2], s[d * 7 + dw][2]);
                s[d * 7 + dw][3] = fmaf(q4.w, win[dw + 3], s[d * 7 + dw][3]);
            }
        }
    }
}

__global__ __launch_bounds__(256, 2) void score_kernel(const float* __restrict__ x)
{
    __shared__ __align__(16) float sH[8 * CH_STRIDE];   // 33 KB
    __shared__ __align__(16) float sX[8 * 256];         // 8 KB
    __shared__ float4 xch[256];                          // 4 KB

    const int tx   = threadIdx.x;
    const int quad = tx & 63;
    const int g    = tx >> 6;
    const int py   = quad >> 2;
    const int qx4  = (quad & 3) * 4;
    const int b  = blockIdx.z;
    const int h0 = blockIdx.y * 16, w0 = blockIdx.x * 16;
    const int h  = h0 + py, wp = w0 + qx4;

    const float* yb  = g_y + (size_t)b * C_ * HW_;
    const float* xbb = x + (size_t)b * C_ * HW_;

    const int NT = (g < 3) ? 14 : 7;      // taps this thread owns
    const int T0 = (g < 3) ? g * 14 : 42; // first global tap index

    float s[14][4];
#pragma unroll
    for (int r = 0; r < 14; r++)
#pragma unroll
        for (int p = 0; p < 4; p++) s[r][p] = 0.0f;

    for (int ch0 = 0; ch0 < 64; ch0 += 8) {
        fill_halo(sH, yb, ch0, h0, w0, tx);
        for (int i = tx; i < 2048; i += 256) {
            const int cc = i >> 8, px = i & 255;
            sX[i] = xbb[(size_t)(ch0 + cc) * HW_ + (h0 + (px >> 4)) * W_ + w0 + (px & 15)];
        }
        __syncthreads();
        if      (g == 0) score_accum<2, 0>(s, sH, sX, quad, py, qx4);
        else if (g == 1) score_accum<2, 2>(s, sH, sX, quad, py, qx4);
        else if (g == 2) score_accum<2, 4>(s, sH, sX, quad, py, qx4);
        else             score_accum<1, 6>(s, sH, sX, quad, py, qx4);
        __syncthreads();
    }

    // 4-way max reduction across dh-groups
    float4 pm = make_float4(-1e30f, -1e30f, -1e30f, -1e30f);
    for (int r = 0; r < NT; r++) {
        pm.x = fmaxf(pm.x, s[r][0]); pm.y = fmaxf(pm.y, s[r][1]);
        pm.z = fmaxf(pm.z, s[r][2]); pm.w = fmaxf(pm.w, s[r][3]);
    }
    xch[tx] = pm;
    __syncthreads();
    float4 m = xch[quad];
#pragma unroll
    for (int gg = 1; gg < 4; gg++) {
        const float4 t = xch[gg * 64 + quad];
        m.x = fmaxf(m.x, t.x); m.y = fmaxf(m.y, t.y);
        m.z = fmaxf(m.z, t.z); m.w = fmaxf(m.w, t.w);
    }
    __syncthreads();

    // exp + 4-way sum reduction
    float4 ps = make_float4(0.f, 0.f, 0.f, 0.f);
    for (int r = 0; r < NT; r++) {
        s[r][0] = __expf(s[r][0] - m.x); ps.x += s[r][0];
        s[r][1] = __expf(s[r][1] - m.y); ps.y += s[r][1];
        s[r][2] = __expf(s[r][2] - m.z); ps.z += s[r][2];
        s[r][3] = __expf(s[r][3] - m.w); ps.w += s[r][3];
    }
    xch[tx] = ps;
    __syncthreads();
    float4 sum = xch[quad];
#pragma unroll
    for (int gg = 1; gg < 4; gg++) {
        const float4 t = xch[gg * 64 + quad];
        sum.x += t.x; sum.y += t.y; sum.z += t.z; sum.w += t.w;
    }
    const float4 inv = make_float4(__frcp_rn(sum.x), __frcp_rn(sum.y),
                                   __frcp_rn(sum.z), __frcp_rn(sum.w));

    float* wb = g_wt + (size_t)b * R_ * HW_ + h * W_ + wp;
    for (int r = 0; r < NT; r++)
        *(float4*)(wb + (size_t)(T0 + r) * HW_) =
            make_float4(s[r][0] * inv.x, s[r][1] * inv.y,
                        s[r][2] * inv.z, s[r][3] * inv.w);
}

// ---------------------------------------------------------------------------
// Kernel 3: weighting. Same quad + dh-group split; partial outputs joined
// through a smem buffer per channel chunk.
// ---------------------------------------------------------------------------
template<int NDH, int DH0>
__device__ __forceinline__ void weight_accum(
    float acc[][4], const float wt[][4], const float* sH, int py, int qx4)
{
#pragma unroll
    for (int o = 0; o < 8; o++) {
        const float* rowb = sH + o * CH_STRIDE + (py + DH0) * HSTR + qx4;
#pragma unroll
        for (int d = 0; d < NDH; d++) {
            float win[12];
            load_win(win, rowb + d * HSTR);
#pragma unroll
            for (int dw = 0; dw < 7; dw++) {
                acc[o][0] = fmaf(wt[d * 7 + dw][0], win[dw + 0], acc[o][0]);
                acc[o][1] = fmaf(wt[d * 7 + dw][1], win[dw + 1], acc[o][1]);
                acc[o][2] = fmaf(wt[d * 7 + dw][2], win[dw + 2], acc[o][2]);
                acc[o][3] = fmaf(wt[d * 7 + dw][3], win[dw + 3], acc[o][3]);
            }
        }
    }
}

__global__ __launch_bounds__(256, 2) void weight_kernel(float* __restrict__ out)
{
    __shared__ __align__(16) float sH[8 * CH_STRIDE];   // 33 KB
    __shared__ float4 pbuf[3 * 8 * 64];                  // 24 KB

    const int tx   = threadIdx.x;
    const int quad = tx & 63;
    const int g    = tx >> 6;
    const int py   = quad >> 2;
    const int qx4  = (quad & 3) * 4;
    const int b  = blockIdx.z;
    const int h0 = blockIdx.y * 16, w0 = blockIdx.x * 16;
    const int h  = h0 + py, wp = w0 + qx4;

    const float* vb  = g_v + (size_t)b * C_ * HW_;
    const float* wtb = g_wt + (size_t)b * R_ * HW_ + h * W_ + wp;

    const int NT = (g < 3) ? 14 : 7;
    const int T0 = (g < 3) ? g * 14 : 42;

    float wt[14][4];
    for (int r = 0; r < NT; r++) {
        const float4 t = *(const float4*)(wtb + (size_t)(T0 + r) * HW_);
        wt[r][0] = t.x; wt[r][1] = t.y; wt[r][2] = t.z; wt[r][3] = t.w;
    }

    float* ob = out + (size_t)b * O_ * HW_ + h * W_ + wp;

    for (int ch0 = 0; ch0 < 64; ch0 += 8) {
        fill_halo(sH, vb, ch0, h0, w0, tx);
        __syncthreads();

        float acc[8][4];
#pragma unroll
        for (int o = 0; o < 8; o++)
#pragma unroll
            for (int p = 0; p < 4; p++) acc[o][p] = 0.0f;

        if      (g == 0) weight_accum<2, 0>(acc, wt, sH, py, qx4);
        else if (g == 1) weight_accum<2, 2>(acc, wt, sH, py, qx4);
        else if (g == 2) weight_accum<2, 4>(acc, wt, sH, py, qx4);
        else             weight_accum<1, 6>(acc, wt, sH, py, qx4);

        if (g > 0) {
#pragma unroll
            for (int o = 0; o < 8; o++)
                pbuf[((g - 1) * 8 + o) * 64 + quad] =
                    make_float4(acc[o][0], acc[o][1], acc[o][2], acc[o][3]);
        }
        __syncthreads();
        if (g == 0) {
#pragma unroll
            for (int o = 0; o < 8; o++) {
                const float4 t1 = pbuf[(0 * 8 + o) * 64 + quad];
                const float4 t2 = pbuf[(1 * 8 + o) * 64 + quad];
                const float4 t3 = pbuf[(2 * 8 + o) * 64 + quad];
                *(float4*)(ob + (size_t)(ch0 + o) * HW_) =
                    make_float4(acc[o][0] + t1.x + t2.x + t3.x,
                                acc[o][1] + t1.y + t2.y + t3.y,
                                acc[o][2] + t1.z + t2.z + t3.z,
                                acc[o][3] + t1.w + t2.w + t3.w);
            }
        }
        __syncthreads();
    }
}

// ---------------------------------------------------------------------------
extern "C" void kernel_launch(void* const* d_in, const int* in_sizes, int n_in,
                              void* d_out, int out_size)
{
    const float* x  = (const float*)d_in[0];
    const float* W1 = (const float*)d_in[1];
    const float* W2 = (const float*)d_in[2];
    const float* W3 = (const float*)d_in[3];
    float* out = (float*)d_out;
    (void)in_sizes; (void)n_in; (void)out_size;

    mat_kernel<<<1, 256>>>(W1, W2);
    qkv_kernel<<<dim3(HW_ / 128, B_), 256>>>(x, W3);
    score_kernel<<<dim3(W_ / 16, H_ / 16, B_), 256>>>(x);
    weight_kernel<<<dim3(W_ / 16, H_ / 16, B_), 256>>>(out);
}